// round 6
// baseline (speedup 1.0000x reference)
#include <cuda_runtime.h>
#include <cuda_bf16.h>
#include <cstdint>

// Problem constants
#define B_  8
#define T_  1024
#define C_  768
#define H_  12
#define HS_ 64
#define M_TOT (B_*T_)        // 8192
#define N_TOT (3*C_)         // 2304
#define K_TOT C_             // 768

// ---------------------------------------------------------------------------
// Device-global scratch: pre-split bf16 hi/lo Q, K, V in [B,H,T,hs] layout
// ---------------------------------------------------------------------------
__device__ __align__(16) __nv_bfloat16 g_Qh[B_*H_*T_*HS_];
__device__ __align__(16) __nv_bfloat16 g_Ql[B_*H_*T_*HS_];
__device__ __align__(16) __nv_bfloat16 g_Kh[B_*H_*T_*HS_];
__device__ __align__(16) __nv_bfloat16 g_Kl[B_*H_*T_*HS_];
__device__ __align__(16) __nv_bfloat16 g_Vh[B_*H_*T_*HS_];
__device__ __align__(16) __nv_bfloat16 g_Vl[B_*H_*T_*HS_];

__device__ __align__(16) __nv_bfloat16 g_xh[M_TOT*K_TOT];
__device__ __align__(16) __nv_bfloat16 g_xl[M_TOT*K_TOT];
__device__ __align__(16) __nv_bfloat16 g_wh[N_TOT*K_TOT];
__device__ __align__(16) __nv_bfloat16 g_wl[N_TOT*K_TOT];

// ---------------------------------------------------------------------------
// PTX helpers (base ISA only)
// ---------------------------------------------------------------------------
__device__ __forceinline__ uint32_t smem_u32(const void* p) {
    uint32_t a;
    asm("{ .reg .u64 t; cvta.to.shared.u64 t, %1; cvt.u32.u64 %0, t; }"
        : "=r"(a) : "l"(p));
    return a;
}
__device__ __forceinline__ void cp_async16(uint32_t s, const void* g) {
    asm volatile("cp.async.cg.shared.global [%0], [%1], 16;" :: "r"(s), "l"(g));
}
__device__ __forceinline__ void cp_commit() {
    asm volatile("cp.async.commit_group;" ::: "memory");
}
__device__ __forceinline__ void cp_wait1() {
    asm volatile("cp.async.wait_group 1;" ::: "memory");
}
__device__ __forceinline__ void cp_wait0() {
    asm volatile("cp.async.wait_group 0;" ::: "memory");
}
__device__ __forceinline__ void ldmatrix_x4(uint32_t& r0, uint32_t& r1,
                                            uint32_t& r2, uint32_t& r3,
                                            uint32_t addr) {
    asm volatile("ldmatrix.sync.aligned.m8n8.x4.shared.b16 {%0,%1,%2,%3}, [%4];"
                 : "=r"(r0), "=r"(r1), "=r"(r2), "=r"(r3) : "r"(addr));
}
__device__ __forceinline__ void ldmatrix_x4_trans(uint32_t& r0, uint32_t& r1,
                                                  uint32_t& r2, uint32_t& r3,
                                                  uint32_t addr) {
    asm volatile("ldmatrix.sync.aligned.m8n8.x4.trans.shared.b16 {%0,%1,%2,%3}, [%4];"
                 : "=r"(r0), "=r"(r1), "=r"(r2), "=r"(r3) : "r"(addr));
}
__device__ __forceinline__ void mma_bf16(float& c0, float& c1, float& c2, float& c3,
                                         uint32_t a0, uint32_t a1, uint32_t a2, uint32_t a3,
                                         uint32_t b0, uint32_t b1) {
    asm volatile(
        "mma.sync.aligned.m16n8k16.row.col.f32.bf16.bf16.f32 "
        "{%0,%1,%2,%3}, {%4,%5,%6,%7}, {%8,%9}, {%0,%1,%2,%3};"
        : "+f"(c0), "+f"(c1), "+f"(c2), "+f"(c3)
        : "r"(a0), "r"(a1), "r"(a2), "r"(a3), "r"(b0), "r"(b1));
}
__device__ __forceinline__ uint32_t pk_bf2(__nv_bfloat16 lo, __nv_bfloat16 hi) {
    __nv_bfloat162 v = __halves2bfloat162(lo, hi);
    return *reinterpret_cast<uint32_t*>(&v);
}
#define SWZ128(o) ((o) ^ (((o) >> 3) & 0x70))

// ---------------------------------------------------------------------------
// Kernel 0: fp32 -> (bf16 hi, bf16 lo) split for x and W
// ---------------------------------------------------------------------------
__global__ __launch_bounds__(256) void split_kernel(const float* __restrict__ x,
                                                    const float* __restrict__ W)
{
    const int nqx = (M_TOT * K_TOT) / 4;
    const int nqw = (N_TOT * K_TOT) / 4;
    for (int q = blockIdx.x * blockDim.x + threadIdx.x; q < nqx + nqw;
         q += gridDim.x * blockDim.x) {
        const float4* src; __nv_bfloat16 *dh, *dl; int qq;
        if (q < nqx) { src = (const float4*)x; dh = g_xh; dl = g_xl; qq = q; }
        else         { src = (const float4*)W; dh = g_wh; dl = g_wl; qq = q - nqx; }
        const float4 v = src[qq];
        __nv_bfloat16 h0 = __float2bfloat16(v.x);
        __nv_bfloat16 h1 = __float2bfloat16(v.y);
        __nv_bfloat16 h2 = __float2bfloat16(v.z);
        __nv_bfloat16 h3 = __float2bfloat16(v.w);
        __nv_bfloat16 l0 = __float2bfloat16(v.x - __bfloat162float(h0));
        __nv_bfloat16 l1 = __float2bfloat16(v.y - __bfloat162float(h1));
        __nv_bfloat16 l2 = __float2bfloat16(v.z - __bfloat162float(h2));
        __nv_bfloat16 l3 = __float2bfloat16(v.w - __bfloat162float(h3));
        __nv_bfloat162* ph = (__nv_bfloat162*)(dh + (size_t)qq * 4);
        __nv_bfloat162* pl = (__nv_bfloat162*)(dl + (size_t)qq * 4);
        ph[0] = __halves2bfloat162(h0, h1);
        ph[1] = __halves2bfloat162(h2, h3);
        pl[0] = __halves2bfloat162(l0, l1);
        pl[1] = __halves2bfloat162(l2, l3);
    }
}

// ---------------------------------------------------------------------------
// Kernel 1: HMMA QKV GEMM v3 — fused passes, chain-broken MMA ordering.
// ---------------------------------------------------------------------------
#define ROWB 80
#define TILE_B (128*ROWB)
#define BUF_B  (4*TILE_B)
#define GEMM_SMEM (2*BUF_B)
#define NITER  24

__global__ __launch_bounds__(256) void qkv_hmma_kernel(const float* __restrict__ bias)
{
    extern __shared__ char smg[];
    const uint32_t sbase = smem_u32(smg);

    const int tid  = threadIdx.x;
    const int warp = tid >> 5;
    const int lane = tid & 31;
    const int m0 = blockIdx.y * 128;
    const int n0 = blockIdx.x * 128;
    const int wm0 = (warp >> 2) * 64;
    const int wn0 = (warp & 3) * 32;

    auto fill = [&](int it, int buf) {
        const int kc = it * 32;
        const uint32_t base = sbase + buf * BUF_B;
        #pragma unroll
        for (int j = 0; j < 8; j++) {
            const int seg = tid + j * 256;
            const int arr = seg >> 9;
            const int w = seg & 511;
            const int r = w >> 2, c = w & 3;
            const __nv_bfloat16* src = (arr == 0) ? g_xh : (arr == 1) ? g_xl
                                     : (arr == 2) ? g_wh : g_wl;
            const int row = ((arr < 2) ? m0 : n0) + r;
            cp_async16(base + arr * TILE_B + r * ROWB + c * 16,
                       src + (size_t)row * K_TOT + kc + c * 8);
        }
        cp_commit();
    };

    float acc[4][4][4] = {};

    fill(0, 0);

    for (int i = 0; i < NITER; i++) {
        const int buf = i & 1;
        if (i + 1 < NITER) fill(i + 1, buf ^ 1);
        if (i + 1 < NITER) cp_wait1(); else cp_wait0();
        __syncthreads();

        const uint32_t sAh = sbase + buf * BUF_B;
        const uint32_t sAl = sAh + TILE_B;
        const uint32_t sBh = sAh + 2 * TILE_B;
        const uint32_t sBl = sAh + 3 * TILE_B;

        uint32_t bh[4][4], bl[4][4];
        #pragma unroll
        for (int nt = 0; nt < 4; nt++) {
            const int off = (wn0 + nt * 8 + (lane & 7)) * ROWB + (lane >> 3) * 16;
            ldmatrix_x4(bh[nt][0], bh[nt][1], bh[nt][2], bh[nt][3], sBh + off);
            ldmatrix_x4(bl[nt][0], bl[nt][1], bl[nt][2], bl[nt][3], sBl + off);
        }

        #pragma unroll
        for (int ks = 0; ks < 2; ks++) {
            #pragma unroll
            for (int mt = 0; mt < 4; mt++) {
                const int off = (wm0 + mt * 16 + (lane & 15)) * ROWB
                              + ks * 32 + (lane >> 4) * 16;
                uint32_t ah0, ah1, ah2, ah3, al0, al1, al2, al3;
                ldmatrix_x4(ah0, ah1, ah2, ah3, sAh + off);
                ldmatrix_x4(al0, al1, al2, al3, sAl + off);
                // pass-grouped nt sweeps: dependent MMAs are distance-4 apart
                #pragma unroll
                for (int nt = 0; nt < 4; nt++)
                    mma_bf16(acc[mt][nt][0], acc[mt][nt][1], acc[mt][nt][2], acc[mt][nt][3],
                             ah0, ah1, ah2, ah3, bh[nt][ks * 2 + 0], bh[nt][ks * 2 + 1]);
                #pragma unroll
                for (int nt = 0; nt < 4; nt++)
                    mma_bf16(acc[mt][nt][0], acc[mt][nt][1], acc[mt][nt][2], acc[mt][nt][3],
                             ah0, ah1, ah2, ah3, bl[nt][ks * 2 + 0], bl[nt][ks * 2 + 1]);
                #pragma unroll
                for (int nt = 0; nt < 4; nt++)
                    mma_bf16(acc[mt][nt][0], acc[mt][nt][1], acc[mt][nt][2], acc[mt][nt][3],
                             al0, al1, al2, al3, bh[nt][ks * 2 + 0], bh[nt][ks * 2 + 1]);
            }
        }
        __syncthreads();
    }

    // Epilogue: bias add + split to bf16 hi/lo, scatter [B,H,T,hs]
    const int g  = lane >> 2;
    const int tq = lane & 3;
    #pragma unroll
    for (int nt = 0; nt < 4; nt++) {
        const int n = n0 + wn0 + nt * 8 + tq * 2;
        const float b0 = __ldg(bias + n);
        const float b1 = __ldg(bias + n + 1);
        const int three = n / C_;
        const int rem   = n - three * C_;
        const int head  = rem >> 6;
        const int d     = rem & 63;
        __nv_bfloat16* dh = (three == 0) ? g_Qh : (three == 1) ? g_Kh : g_Vh;
        __nv_bfloat16* dl = (three == 0) ? g_Ql : (three == 1) ? g_Kl : g_Vl;
        #pragma unroll
        for (int mt = 0; mt < 4; mt++) {
            #pragma unroll
            for (int half = 0; half < 2; half++) {
                const int m = m0 + wm0 + mt * 16 + g + half * 8;
                const int bb = m >> 10;
                const int t  = m & 1023;
                const float f0 = acc[mt][nt][half * 2 + 0] + b0;
                const float f1 = acc[mt][nt][half * 2 + 1] + b1;
                const __nv_bfloat16 h0 = __float2bfloat16(f0);
                const __nv_bfloat16 h1 = __float2bfloat16(f1);
                const __nv_bfloat16 l0 = __float2bfloat16(f0 - __bfloat162float(h0));
                const __nv_bfloat16 l1 = __float2bfloat16(f1 - __bfloat162float(h1));
                const size_t idx = ((size_t)(bb * H_ + head) * T_ + t) * HS_ + d;
                *reinterpret_cast<__nv_bfloat162*>(dh + idx) = __halves2bfloat162(h0, h1);
                *reinterpret_cast<__nv_bfloat162*>(dl + idx) = __halves2bfloat162(l0, l1);
            }
        }
    }
}

// ---------------------------------------------------------------------------
// Kernel 2: fused causal ReLU attention, chain-broken MMA ordering.
// ---------------------------------------------------------------------------
#define AT_BUF0  16384
#define AT_BUF_B 32768
#define AT_SMEM  81920

__global__ __launch_bounds__(128) void attn_hmma_kernel(float* __restrict__ out)
{
    extern __shared__ char smema[];
    const uint32_t sb = smem_u32(smema);
    const int tid  = threadIdx.x;
    const int warp = tid >> 5;
    const int lane = tid & 31;
    const int bh = blockIdx.x;
    const int qt = blockIdx.y;
    const int b  = bh / H_;
    const int h  = bh - b * H_;
    const size_t hbase = (size_t)bh * T_ * HS_;

    {
        #pragma unroll
        for (int j = 0; j < 8; j++) {
            const int seg = tid + j * 128;
            const int arr = seg >> 9;
            const int w = seg & 511;
            const int r = w >> 3, c = w & 7;
            const __nv_bfloat16* src = arr ? g_Ql : g_Qh;
            cp_async16(sb + arr * 8192 + SWZ128(r * 128 + c * 16),
                       src + hbase + (size_t)(qt * 64 + r) * HS_ + c * 8);
        }
    }
    auto fillkv = [&](int kt, int buf) {
        #pragma unroll
        for (int j = 0; j < 16; j++) {
            const int seg = tid + j * 128;
            const int arr = seg >> 9;
            const int w = seg & 511;
            const int r = w >> 3, c = w & 7;
            const __nv_bfloat16* src = (arr == 0) ? g_Kh : (arr == 1) ? g_Kl
                                     : (arr == 2) ? g_Vh : g_Vl;
            cp_async16(sb + AT_BUF0 + buf * AT_BUF_B + arr * 8192
                           + SWZ128(r * 128 + c * 16),
                       src + hbase + (size_t)(kt * 64 + r) * HS_ + c * 8);
        }
        cp_commit();
    };

    fillkv(0, 0);

    float y[8][4] = {};
    const float scale = 0.125f;
    const int rlo = warp * 16 + (lane >> 2);
    const int cbase = 2 * (lane & 3);

    for (int kt = 0; kt <= qt; kt++) {
        const int buf = kt & 1;
        if (kt < qt) { fillkv(kt + 1, buf ^ 1); cp_wait1(); }
        else         { cp_wait0(); }
        __syncthreads();

        const uint32_t sQh = sb, sQl = sb + 8192;
        const uint32_t sK0 = sb + AT_BUF0 + buf * AT_BUF_B;
        const uint32_t sKh = sK0, sKl = sK0 + 8192;
        const uint32_t sVh = sK0 + 16384, sVl = sK0 + 24576;

        // ---- S = Q·K^T, 3 passes; B frags cached per kp, dist-8 chains
        float S[8][4] = {};
        #pragma unroll
        for (int p = 0; p < 3; p++) {
            const uint32_t qb = (p == 2) ? sQl : sQh;
            const uint32_t kb = (p == 1) ? sKl : sKh;
            uint32_t af[4][4];
            #pragma unroll
            for (int ks = 0; ks < 4; ks++) {
                const int row = warp * 16 + (lane & 15);
                const int colb = ks * 32 + (lane >> 4) * 16;
                ldmatrix_x4(af[ks][0], af[ks][1], af[ks][2], af[ks][3],
                            qb + SWZ128(row * 128 + colb));
            }
            #pragma unroll
            for (int kp = 0; kp < 2; kp++) {
                uint32_t bs[8][4];
                #pragma unroll
                for (int nt = 0; nt < 8; nt++) {
                    const int row = nt * 8 + (lane & 7);
                    const int colb = kp * 64 + (lane >> 3) * 16;
                    ldmatrix_x4(bs[nt][0], bs[nt][1], bs[nt][2], bs[nt][3],
                                kb + SWZ128(row * 128 + colb));
                }
                #pragma unroll
                for (int nt = 0; nt < 8; nt++)
                    mma_bf16(S[nt][0], S[nt][1], S[nt][2], S[nt][3],
                             af[2*kp][0], af[2*kp][1], af[2*kp][2], af[2*kp][3],
                             bs[nt][0], bs[nt][1]);
                #pragma unroll
                for (int nt = 0; nt < 8; nt++)
                    mma_bf16(S[nt][0], S[nt][1], S[nt][2], S[nt][3],
                             af[2*kp+1][0], af[2*kp+1][1], af[2*kp+1][2], af[2*kp+1][3],
                             bs[nt][2], bs[nt][3]);
            }
        }

        // ---- P = relu(scale*S) + causal mask; split + repack to A frags
        const bool diag = (kt == qt);
        uint32_t pha[4][4], pla[4][4];
        #pragma unroll
        for (int ksp = 0; ksp < 4; ksp++) {
            #pragma unroll
            for (int u = 0; u < 2; u++) {
                const int ntile = 2 * ksp + u;
                float pv[4];
                #pragma unroll
                for (int c = 0; c < 4; c++) {
                    float v = fmaxf(S[ntile][c] * scale, 0.0f);
                    if (diag) {
                        const int col = ntile * 8 + cbase + (c & 1);
                        const int row = rlo + ((c >= 2) ? 8 : 0);
                        if (col > row) v = 0.0f;
                    }
                    pv[c] = v;
                }
                __nv_bfloat16 h0 = __float2bfloat16(pv[0]);
                __nv_bfloat16 h1 = __float2bfloat16(pv[1]);
                __nv_bfloat16 h2 = __float2bfloat16(pv[2]);
                __nv_bfloat16 h3 = __float2bfloat16(pv[3]);
                pha[ksp][2*u + 0] = pk_bf2(h0, h1);
                pha[ksp][2*u + 1] = pk_bf2(h2, h3);
                pla[ksp][2*u + 0] = pk_bf2(
                    __float2bfloat16(pv[0] - __bfloat162float(h0)),
                    __float2bfloat16(pv[1] - __bfloat162float(h1)));
                pla[ksp][2*u + 1] = pk_bf2(
                    __float2bfloat16(pv[2] - __bfloat162float(h2)),
                    __float2bfloat16(pv[3] - __bfloat162float(h3)));
            }
        }

        // ---- y += P·V, 3 passes; V frags cached per kp, dist-8 chains
        #pragma unroll
        for (int p = 0; p < 3; p++) {
            const uint32_t vb = (p == 1) ? sVl : sVh;
            const uint32_t (*pa)[4] = (p == 2) ? pla : pha;
            #pragma unroll
            for (int kp = 0; kp < 2; kp++) {
                uint32_t bv[8][4];
                #pragma unroll
                for (int nt = 0; nt < 8; nt++) {
                    const int row = kp * 32 + (lane >> 3) * 8 + (lane & 7);
                    const int colb = nt * 16;
                    ldmatrix_x4_trans(bv[nt][0], bv[nt][1], bv[nt][2], bv[nt][3],
                                      vb + SWZ128(row * 128 + colb));
                }
                #pragma unroll
                for (int nt = 0; nt < 8; nt++)
                    mma_bf16(y[nt][0], y[nt][1], y[nt][2], y[nt][3],
                             pa[2*kp][0], pa[2*kp][1], pa[2*kp][2], pa[2*kp][3],
                             bv[nt][0], bv[nt][1]);
                #pragma unroll
                for (int nt = 0; nt < 8; nt++)
                    mma_bf16(y[nt][0], y[nt][1], y[nt][2], y[nt][3],
                             pa[2*kp+1][0], pa[2*kp+1][1], pa[2*kp+1][2], pa[2*kp+1][3],
                             bv[nt][2], bv[nt][3]);
            }
        }
        __syncthreads();
    }

    const int g = lane >> 2;
    #pragma unroll
    for (int nt = 0; nt < 8; nt++) {
        const int col = h * HS_ + nt * 8 + cbase;
        const int t0 = qt * 64 + warp * 16 + g;
        float2 v0; v0.x = y[nt][0]; v0.y = y[nt][1];
        float2 v1; v1.x = y[nt][2]; v1.y = y[nt][3];
        *reinterpret_cast<float2*>(out + ((size_t)b * T_ + t0) * C_ + col) = v0;
        *reinterpret_cast<float2*>(out + ((size_t)b * T_ + t0 + 8) * C_ + col) = v1;
    }
}

// ---------------------------------------------------------------------------
extern "C" void kernel_launch(void* const* d_in, const int* in_sizes, int n_in,
                              void* d_out, int out_size)
{
    const float* x    = (const float*)d_in[0];
    const float* W    = (const float*)d_in[1];
    const float* bias = (const float*)d_in[2];
    float* out = (float*)d_out;

    split_kernel<<<1184, 256>>>(x, W);

    cudaFuncSetAttribute(qkv_hmma_kernel,
                         cudaFuncAttributeMaxDynamicSharedMemorySize, GEMM_SMEM);
    qkv_hmma_kernel<<<dim3(N_TOT / 128, M_TOT / 128), 256, GEMM_SMEM>>>(bias);

    cudaFuncSetAttribute(attn_hmma_kernel,
                         cudaFuncAttributeMaxDynamicSharedMemorySize, AT_SMEM);
    attn_hmma_kernel<<<dim3(B_ * H_, T_ / 64), 128, AT_SMEM>>>(out);
}

// round 7
// speedup vs baseline: 1.6165x; 1.6165x over previous
#include <cuda_runtime.h>
#include <cuda_fp16.h>
#include <cstdint>

// Problem constants
#define B_  8
#define T_  1024
#define C_  768
#define H_  12
#define HS_ 64
#define M_TOT (B_*T_)        // 8192
#define N_TOT (3*C_)         // 2304
#define K_TOT C_             // 768

// ---------------------------------------------------------------------------
// Device-global scratch (fp16): Q needs hi/lo split (A operand), K/V single.
// ---------------------------------------------------------------------------
__device__ __align__(16) __half g_Qh[B_*H_*T_*HS_];
__device__ __align__(16) __half g_Ql[B_*H_*T_*HS_];
__device__ __align__(16) __half g_K16[B_*H_*T_*HS_];
__device__ __align__(16) __half g_V16[B_*H_*T_*HS_];

__device__ __align__(16) __half g_xh[M_TOT*K_TOT];
__device__ __align__(16) __half g_xl[M_TOT*K_TOT];
__device__ __align__(16) __half g_w16[N_TOT*K_TOT];

// ---------------------------------------------------------------------------
// PTX helpers (base ISA only)
// ---------------------------------------------------------------------------
__device__ __forceinline__ uint32_t smem_u32(const void* p) {
    uint32_t a;
    asm("{ .reg .u64 t; cvta.to.shared.u64 t, %1; cvt.u32.u64 %0, t; }"
        : "=r"(a) : "l"(p));
    return a;
}
__device__ __forceinline__ void cp_async16(uint32_t s, const void* g) {
    asm volatile("cp.async.cg.shared.global [%0], [%1], 16;" :: "r"(s), "l"(g));
}
__device__ __forceinline__ void cp_commit() {
    asm volatile("cp.async.commit_group;" ::: "memory");
}
__device__ __forceinline__ void cp_wait1() {
    asm volatile("cp.async.wait_group 1;" ::: "memory");
}
__device__ __forceinline__ void cp_wait0() {
    asm volatile("cp.async.wait_group 0;" ::: "memory");
}
__device__ __forceinline__ void ldmatrix_x4(uint32_t& r0, uint32_t& r1,
                                            uint32_t& r2, uint32_t& r3,
                                            uint32_t addr) {
    asm volatile("ldmatrix.sync.aligned.m8n8.x4.shared.b16 {%0,%1,%2,%3}, [%4];"
                 : "=r"(r0), "=r"(r1), "=r"(r2), "=r"(r3) : "r"(addr));
}
__device__ __forceinline__ void ldmatrix_x4_trans(uint32_t& r0, uint32_t& r1,
                                                  uint32_t& r2, uint32_t& r3,
                                                  uint32_t addr) {
    asm volatile("ldmatrix.sync.aligned.m8n8.x4.trans.shared.b16 {%0,%1,%2,%3}, [%4];"
                 : "=r"(r0), "=r"(r1), "=r"(r2), "=r"(r3) : "r"(addr));
}
__device__ __forceinline__ void mma_f16(float& c0, float& c1, float& c2, float& c3,
                                        uint32_t a0, uint32_t a1, uint32_t a2, uint32_t a3,
                                        uint32_t b0, uint32_t b1) {
    asm volatile(
        "mma.sync.aligned.m16n8k16.row.col.f32.f16.f16.f32 "
        "{%0,%1,%2,%3}, {%4,%5,%6,%7}, {%8,%9}, {%0,%1,%2,%3};"
        : "+f"(c0), "+f"(c1), "+f"(c2), "+f"(c3)
        : "r"(a0), "r"(a1), "r"(a2), "r"(a3), "r"(b0), "r"(b1));
}
__device__ __forceinline__ uint32_t pk_h2(__half lo, __half hi) {
    __half2 v = __halves2half2(lo, hi);
    return *reinterpret_cast<uint32_t*>(&v);
}
#define SWZ128(o) ((o) ^ (((o) >> 3) & 0x70))

// ---------------------------------------------------------------------------
// Kernel 0: fp32 x -> (fp16 hi, fp16 lo); fp32 W -> fp16 single
// ---------------------------------------------------------------------------
__global__ __launch_bounds__(256) void split_kernel(const float* __restrict__ x,
                                                    const float* __restrict__ W)
{
    const int nqx = (M_TOT * K_TOT) / 4;
    const int nqw = (N_TOT * K_TOT) / 4;
    for (int q = blockIdx.x * blockDim.x + threadIdx.x; q < nqx + nqw;
         q += gridDim.x * blockDim.x) {
        if (q < nqx) {
            const float4 v = ((const float4*)x)[q];
            __half h0 = __float2half_rn(v.x);
            __half h1 = __float2half_rn(v.y);
            __half h2 = __float2half_rn(v.z);
            __half h3 = __float2half_rn(v.w);
            __half l0 = __float2half_rn(v.x - __half2float(h0));
            __half l1 = __float2half_rn(v.y - __half2float(h1));
            __half l2 = __float2half_rn(v.z - __half2float(h2));
            __half l3 = __float2half_rn(v.w - __half2float(h3));
            __half2* ph = (__half2*)(g_xh + (size_t)q * 4);
            __half2* pl = (__half2*)(g_xl + (size_t)q * 4);
            ph[0] = __halves2half2(h0, h1);
            ph[1] = __halves2half2(h2, h3);
            pl[0] = __halves2half2(l0, l1);
            pl[1] = __halves2half2(l2, l3);
        } else {
            const int qq = q - nqx;
            const float4 v = ((const float4*)W)[qq];
            __half2* pw = (__half2*)(g_w16 + (size_t)qq * 4);
            pw[0] = __halves2half2(__float2half_rn(v.x), __float2half_rn(v.y));
            pw[1] = __halves2half2(__float2half_rn(v.z), __float2half_rn(v.w));
        }
    }
}

// ---------------------------------------------------------------------------
// Kernel 1: HMMA QKV GEMM — fp16, 2 fused precision passes (Ah·W + Al·W).
// CTA tile 128x128, BK=32, 256 threads = 8 warps (2m x 4n), warp tile 64x32.
// ---------------------------------------------------------------------------
#define ROWB 80
#define TILE_B (128*ROWB)        // 10240 B per operand tile
#define BUF_B  (3*TILE_B)        // Ah + Al + B16 per buffer = 30720 B
#define GEMM_SMEM (2*BUF_B)      // 61440 B
#define NITER  24

__global__ __launch_bounds__(256) void qkv_hmma_kernel(const float* __restrict__ bias)
{
    extern __shared__ char smg[];
    const uint32_t sbase = smem_u32(smg);

    const int tid  = threadIdx.x;
    const int warp = tid >> 5;
    const int lane = tid & 31;
    const int m0 = blockIdx.y * 128;
    const int n0 = blockIdx.x * 128;
    const int wm0 = (warp >> 2) * 64;
    const int wn0 = (warp & 3) * 32;

    auto fill = [&](int it, int buf) {
        const int kc = it * 32;
        const uint32_t base = sbase + buf * BUF_B;
        #pragma unroll
        for (int j = 0; j < 6; j++) {
            const int seg = tid + j * 256;        // 0..1535
            const int arr = seg >> 9;             // 0:Ah 1:Al 2:B16
            const int w = seg & 511;
            const int r = w >> 2, c = w & 3;      // row 0..127, 16B chunk 0..3
            const __half* src = (arr == 0) ? g_xh : (arr == 1) ? g_xl : g_w16;
            const int row = ((arr < 2) ? m0 : n0) + r;
            cp_async16(base + arr * TILE_B + r * ROWB + c * 16,
                       src + (size_t)row * K_TOT + kc + c * 8);
        }
        cp_commit();
    };

    float acc[4][4][4] = {};

    fill(0, 0);

    for (int i = 0; i < NITER; i++) {
        const int buf = i & 1;
        if (i + 1 < NITER) fill(i + 1, buf ^ 1);
        if (i + 1 < NITER) cp_wait1(); else cp_wait0();
        __syncthreads();

        const uint32_t sAh = sbase + buf * BUF_B;
        const uint32_t sAl = sAh + TILE_B;
        const uint32_t sB  = sAh + 2 * TILE_B;

        uint32_t bf[4][4];
        #pragma unroll
        for (int nt = 0; nt < 4; nt++) {
            const int off = (wn0 + nt * 8 + (lane & 7)) * ROWB + (lane >> 3) * 16;
            ldmatrix_x4(bf[nt][0], bf[nt][1], bf[nt][2], bf[nt][3], sB + off);
        }

        #pragma unroll
        for (int ks = 0; ks < 2; ks++) {
            #pragma unroll
            for (int mt = 0; mt < 4; mt++) {
                const int off = (wm0 + mt * 16 + (lane & 15)) * ROWB
                              + ks * 32 + (lane >> 4) * 16;
                uint32_t ah0, ah1, ah2, ah3, al0, al1, al2, al3;
                ldmatrix_x4(ah0, ah1, ah2, ah3, sAh + off);
                ldmatrix_x4(al0, al1, al2, al3, sAl + off);
                #pragma unroll
                for (int nt = 0; nt < 4; nt++) {
                    float* c = acc[mt][nt];
                    mma_f16(c[0], c[1], c[2], c[3], ah0, ah1, ah2, ah3,
                            bf[nt][ks * 2 + 0], bf[nt][ks * 2 + 1]);
                    mma_f16(c[0], c[1], c[2], c[3], al0, al1, al2, al3,
                            bf[nt][ks * 2 + 0], bf[nt][ks * 2 + 1]);
                }
            }
        }
        __syncthreads();
    }

    // Epilogue: bias add; Q -> fp16 hi/lo split; K,V -> fp16 single.
    const int g  = lane >> 2;
    const int tq = lane & 3;
    #pragma unroll
    for (int nt = 0; nt < 4; nt++) {
        const int n = n0 + wn0 + nt * 8 + tq * 2;
        const float b0 = __ldg(bias + n);
        const float b1 = __ldg(bias + n + 1);
        const int three = n / C_;
        const int rem   = n - three * C_;
        const int head  = rem >> 6;
        const int d     = rem & 63;
        #pragma unroll
        for (int mt = 0; mt < 4; mt++) {
            #pragma unroll
            for (int half = 0; half < 2; half++) {
                const int m = m0 + wm0 + mt * 16 + g + half * 8;
                const int bb = m >> 10;
                const int t  = m & 1023;
                const float f0 = acc[mt][nt][half * 2 + 0] + b0;
                const float f1 = acc[mt][nt][half * 2 + 1] + b1;
                const size_t idx = ((size_t)(bb * H_ + head) * T_ + t) * HS_ + d;
                const __half h0 = __float2half_rn(f0);
                const __half h1 = __float2half_rn(f1);
                if (three == 0) {
                    const __half l0 = __float2half_rn(f0 - __half2float(h0));
                    const __half l1 = __float2half_rn(f1 - __half2float(h1));
                    *reinterpret_cast<__half2*>(g_Qh + idx) = __halves2half2(h0, h1);
                    *reinterpret_cast<__half2*>(g_Ql + idx) = __halves2half2(l0, l1);
                } else {
                    __half* dst = (three == 1) ? g_K16 : g_V16;
                    *reinterpret_cast<__half2*>(dst + idx) = __halves2half2(h0, h1);
                }
            }
        }
    }
}

// ---------------------------------------------------------------------------
// Kernel 2: fused causal ReLU attention — fp16, 2 passes per GEMM.
// smem: Qh|Ql (16KB) + 2 x (K16|V16) buffers (2 x 16KB) = 48KB.
// ---------------------------------------------------------------------------
#define AT_BUF0  16384
#define AT_BUF_B 16384
#define AT_SMEM  49152

__global__ __launch_bounds__(128) void attn_hmma_kernel(float* __restrict__ out)
{
    extern __shared__ char smema[];
    const uint32_t sb = smem_u32(smema);
    const int tid  = threadIdx.x;
    const int warp = tid >> 5;
    const int lane = tid & 31;
    const int bh = blockIdx.x;
    const int qt = blockIdx.y;
    const int b  = bh / H_;
    const int h  = bh - b * H_;
    const size_t hbase = (size_t)bh * T_ * HS_;

    // ---- load Q tile (hi+lo), swizzled 128B rows
    {
        #pragma unroll
        for (int j = 0; j < 8; j++) {
            const int seg = tid + j * 128;          // 0..1023
            const int arr = seg >> 9;               // 0:Qh 1:Ql
            const int w = seg & 511;
            const int r = w >> 3, c = w & 7;
            const __half* src = arr ? g_Ql : g_Qh;
            cp_async16(sb + arr * 8192 + SWZ128(r * 128 + c * 16),
                       src + hbase + (size_t)(qt * 64 + r) * HS_ + c * 8);
        }
    }
    auto fillkv = [&](int kt, int buf) {
        #pragma unroll
        for (int j = 0; j < 8; j++) {
            const int seg = tid + j * 128;          // 0..1023
            const int arr = seg >> 9;               // 0:K16 1:V16
            const int w = seg & 511;
            const int r = w >> 3, c = w & 7;
            const __half* src = arr ? g_V16 : g_K16;
            cp_async16(sb + AT_BUF0 + buf * AT_BUF_B + arr * 8192
                           + SWZ128(r * 128 + c * 16),
                       src + hbase + (size_t)(kt * 64 + r) * HS_ + c * 8);
        }
        cp_commit();
    };

    fillkv(0, 0);   // Q loads ride in this group

    float y[8][4] = {};
    const float scale = 0.125f;
    const int rlo = warp * 16 + (lane >> 2);
    const int cbase = 2 * (lane & 3);

    for (int kt = 0; kt <= qt; kt++) {
        const int buf = kt & 1;
        if (kt < qt) { fillkv(kt + 1, buf ^ 1); cp_wait1(); }
        else         { cp_wait0(); }
        __syncthreads();

        const uint32_t sQh = sb, sQl = sb + 8192;
        const uint32_t sK = sb + AT_BUF0 + buf * AT_BUF_B;
        const uint32_t sV = sK + 8192;

        // ---- S = (Qh + Ql) · K16^T, 2 passes
        float S[8][4] = {};
        #pragma unroll
        for (int p = 0; p < 2; p++) {
            const uint32_t qb = p ? sQl : sQh;
            uint32_t af[4][4];
            #pragma unroll
            for (int ks = 0; ks < 4; ks++) {
                const int row = warp * 16 + (lane & 15);
                const int colb = ks * 32 + (lane >> 4) * 16;
                ldmatrix_x4(af[ks][0], af[ks][1], af[ks][2], af[ks][3],
                            qb + SWZ128(row * 128 + colb));
            }
            #pragma unroll
            for (int kp = 0; kp < 2; kp++) {
                uint32_t bs[8][4];
                #pragma unroll
                for (int nt = 0; nt < 8; nt++) {
                    const int row = nt * 8 + (lane & 7);
                    const int colb = kp * 64 + (lane >> 3) * 16;
                    ldmatrix_x4(bs[nt][0], bs[nt][1], bs[nt][2], bs[nt][3],
                                sK + SWZ128(row * 128 + colb));
                }
                #pragma unroll
                for (int nt = 0; nt < 8; nt++) {
                    mma_f16(S[nt][0], S[nt][1], S[nt][2], S[nt][3],
                            af[2*kp][0], af[2*kp][1], af[2*kp][2], af[2*kp][3],
                            bs[nt][0], bs[nt][1]);
                    mma_f16(S[nt][0], S[nt][1], S[nt][2], S[nt][3],
                            af[2*kp+1][0], af[2*kp+1][1], af[2*kp+1][2], af[2*kp+1][3],
                            bs[nt][2], bs[nt][3]);
                }
            }
        }

        // ---- P = relu(scale*S), causal mask; split fp16 + repack to A frags
        const bool diag = (kt == qt);
        uint32_t pha[4][4], pla[4][4];
        #pragma unroll
        for (int ksp = 0; ksp < 4; ksp++) {
            #pragma unroll
            for (int u = 0; u < 2; u++) {
                const int ntile = 2 * ksp + u;
                float pv[4];
                #pragma unroll
                for (int c = 0; c < 4; c++) {
                    float v = fmaxf(S[ntile][c] * scale, 0.0f);
                    if (diag) {
                        const int col = ntile * 8 + cbase + (c & 1);
                        const int row = rlo + ((c >= 2) ? 8 : 0);
                        if (col > row) v = 0.0f;
                    }
                    pv[c] = v;
                }
                __half h0 = __float2half_rn(pv[0]);
                __half h1 = __float2half_rn(pv[1]);
                __half h2 = __float2half_rn(pv[2]);
                __half h3 = __float2half_rn(pv[3]);
                pha[ksp][2*u + 0] = pk_h2(h0, h1);
                pha[ksp][2*u + 1] = pk_h2(h2, h3);
                pla[ksp][2*u + 0] = pk_h2(
                    __float2half_rn(pv[0] - __half2float(h0)),
                    __float2half_rn(pv[1] - __half2float(h1)));
                pla[ksp][2*u + 1] = pk_h2(
                    __float2half_rn(pv[2] - __half2float(h2)),
                    __float2half_rn(pv[3] - __half2float(h3)));
            }
        }

        // ---- y += (Ph + Pl) · V16, 2 passes; V frags via ldmatrix.trans
        #pragma unroll
        for (int p = 0; p < 2; p++) {
            const uint32_t (*pa)[4] = p ? pla : pha;
            #pragma unroll
            for (int kp = 0; kp < 2; kp++) {
                uint32_t bv[8][4];
                #pragma unroll
                for (int nt = 0; nt < 8; nt++) {
                    const int row = kp * 32 + (lane >> 3) * 8 + (lane & 7);
                    const int colb = nt * 16;
                    ldmatrix_x4_trans(bv[nt][0], bv[nt][1], bv[nt][2], bv[nt][3],
                                      sV + SWZ128(row * 128 + colb));
                }
                #pragma unroll
                for (int nt = 0; nt < 8; nt++) {
                    mma_f16(y[nt][0], y[nt][1], y[nt][2], y[nt][3],
                            pa[2*kp][0], pa[2*kp][1], pa[2*kp][2], pa[2*kp][3],
                            bv[nt][0], bv[nt][1]);
                    mma_f16(y[nt][0], y[nt][1], y[nt][2], y[nt][3],
                            pa[2*kp+1][0], pa[2*kp+1][1], pa[2*kp+1][2], pa[2*kp+1][3],
                            bv[nt][2], bv[nt][3]);
                }
            }
        }
        __syncthreads();
    }

    const int g = lane >> 2;
    #pragma unroll
    for (int nt = 0; nt < 8; nt++) {
        const int col = h * HS_ + nt * 8 + cbase;
        const int t0 = qt * 64 + warp * 16 + g;
        float2 v0; v0.x = y[nt][0]; v0.y = y[nt][1];
        float2 v1; v1.x = y[nt][2]; v1.y = y[nt][3];
        *reinterpret_cast<float2*>(out + ((size_t)b * T_ + t0) * C_ + col) = v0;
        *reinterpret_cast<float2*>(out + ((size_t)b * T_ + t0 + 8) * C_ + col) = v1;
    }
}

// ---------------------------------------------------------------------------
extern "C" void kernel_launch(void* const* d_in, const int* in_sizes, int n_in,
                              void* d_out, int out_size)
{
    const float* x    = (const float*)d_in[0];
    const float* W    = (const float*)d_in[1];
    const float* bias = (const float*)d_in[2];
    float* out = (float*)d_out;

    split_kernel<<<1184, 256>>>(x, W);

    cudaFuncSetAttribute(qkv_hmma_kernel,
                         cudaFuncAttributeMaxDynamicSharedMemorySize, GEMM_SMEM);
    qkv_hmma_kernel<<<dim3(N_TOT / 128, M_TOT / 128), 256, GEMM_SMEM>>>(bias);

    cudaFuncSetAttribute(attn_hmma_kernel,
                         cudaFuncAttributeMaxDynamicSharedMemorySize, AT_SMEM);
    attn_hmma_kernel<<<dim3(B_ * H_, T_ / 64), 128, AT_SMEM>>>(out);
}

// round 8
// speedup vs baseline: 2.2060x; 1.3647x over previous
#include <cuda_runtime.h>
#include <cuda_fp16.h>
#include <cstdint>

// Problem constants
#define B_  8
#define T_  1024
#define C_  768
#define H_  12
#define HS_ 64
#define M_TOT (B_*T_)        // 8192
#define N_TOT (3*C_)         // 2304
#define K_TOT C_             // 768

// ---------------------------------------------------------------------------
// Device-global scratch (fp16): Q keeps hi/lo split (attn A operand), K/V single.
// ---------------------------------------------------------------------------
__device__ __align__(16) __half g_Qh[B_*H_*T_*HS_];
__device__ __align__(16) __half g_Ql[B_*H_*T_*HS_];
__device__ __align__(16) __half g_K16[B_*H_*T_*HS_];
__device__ __align__(16) __half g_V16[B_*H_*T_*HS_];

__device__ __align__(16) __half g_x16[M_TOT*K_TOT];
__device__ __align__(16) __half g_w16[N_TOT*K_TOT];

// ---------------------------------------------------------------------------
// PTX helpers (base ISA only)
// ---------------------------------------------------------------------------
__device__ __forceinline__ uint32_t smem_u32(const void* p) {
    uint32_t a;
    asm("{ .reg .u64 t; cvta.to.shared.u64 t, %1; cvt.u32.u64 %0, t; }"
        : "=r"(a) : "l"(p));
    return a;
}
__device__ __forceinline__ void cp_async16(uint32_t s, const void* g) {
    asm volatile("cp.async.cg.shared.global [%0], [%1], 16;" :: "r"(s), "l"(g));
}
__device__ __forceinline__ void cp_commit() {
    asm volatile("cp.async.commit_group;" ::: "memory");
}
__device__ __forceinline__ void cp_wait1() {
    asm volatile("cp.async.wait_group 1;" ::: "memory");
}
__device__ __forceinline__ void cp_wait0() {
    asm volatile("cp.async.wait_group 0;" ::: "memory");
}
__device__ __forceinline__ void ldmatrix_x4(uint32_t& r0, uint32_t& r1,
                                            uint32_t& r2, uint32_t& r3,
                                            uint32_t addr) {
    asm volatile("ldmatrix.sync.aligned.m8n8.x4.shared.b16 {%0,%1,%2,%3}, [%4];"
                 : "=r"(r0), "=r"(r1), "=r"(r2), "=r"(r3) : "r"(addr));
}
__device__ __forceinline__ void ldmatrix_x4_trans(uint32_t& r0, uint32_t& r1,
                                                  uint32_t& r2, uint32_t& r3,
                                                  uint32_t addr) {
    asm volatile("ldmatrix.sync.aligned.m8n8.x4.trans.shared.b16 {%0,%1,%2,%3}, [%4];"
                 : "=r"(r0), "=r"(r1), "=r"(r2), "=r"(r3) : "r"(addr));
}
__device__ __forceinline__ void mma_f16(float& c0, float& c1, float& c2, float& c3,
                                        uint32_t a0, uint32_t a1, uint32_t a2, uint32_t a3,
                                        uint32_t b0, uint32_t b1) {
    asm volatile(
        "mma.sync.aligned.m16n8k16.row.col.f32.f16.f16.f32 "
        "{%0,%1,%2,%3}, {%4,%5,%6,%7}, {%8,%9}, {%0,%1,%2,%3};"
        : "+f"(c0), "+f"(c1), "+f"(c2), "+f"(c3)
        : "r"(a0), "r"(a1), "r"(a2), "r"(a3), "r"(b0), "r"(b1));
}
__device__ __forceinline__ uint32_t pk_h2(__half lo, __half hi) {
    __half2 v = __halves2half2(lo, hi);
    return *reinterpret_cast<uint32_t*>(&v);
}
#define SWZ128(o) ((o) ^ (((o) >> 3) & 0x70))

// ---------------------------------------------------------------------------
// Kernel 0: fp32 -> fp16 single plane for x and W
// ---------------------------------------------------------------------------
__global__ __launch_bounds__(256) void split_kernel(const float* __restrict__ x,
                                                    const float* __restrict__ W)
{
    const int nqx = (M_TOT * K_TOT) / 4;
    const int nqw = (N_TOT * K_TOT) / 4;
    for (int q = blockIdx.x * blockDim.x + threadIdx.x; q < nqx + nqw;
         q += gridDim.x * blockDim.x) {
        const float4* src; __half* dst; int qq;
        if (q < nqx) { src = (const float4*)x; dst = g_x16; qq = q; }
        else         { src = (const float4*)W; dst = g_w16; qq = q - nqx; }
        const float4 v = src[qq];
        __half2* p = (__half2*)(dst + (size_t)qq * 4);
        p[0] = __halves2half2(__float2half_rn(v.x), __float2half_rn(v.y));
        p[1] = __halves2half2(__float2half_rn(v.z), __float2half_rn(v.w));
    }
}

// ---------------------------------------------------------------------------
// Kernel 1: HMMA QKV GEMM — fp16 single pass (x16 · w16).
// CTA tile 128x128, BK=32, 256 threads = 8 warps (2m x 4n), warp tile 64x32.
// ---------------------------------------------------------------------------
#define ROWB 80
#define TILE_B (128*ROWB)        // 10240 B per operand tile
#define BUF_B  (2*TILE_B)        // A + B per buffer = 20480 B
#define GEMM_SMEM (2*BUF_B)      // 40960 B
#define NITER  24

__global__ __launch_bounds__(256) void qkv_hmma_kernel(const float* __restrict__ bias)
{
    extern __shared__ char smg[];
    const uint32_t sbase = smem_u32(smg);

    const int tid  = threadIdx.x;
    const int warp = tid >> 5;
    const int lane = tid & 31;
    const int m0 = blockIdx.y * 128;
    const int n0 = blockIdx.x * 128;
    const int wm0 = (warp >> 2) * 64;
    const int wn0 = (warp & 3) * 32;

    auto fill = [&](int it, int buf) {
        const int kc = it * 32;
        const uint32_t base = sbase + buf * BUF_B;
        #pragma unroll
        for (int j = 0; j < 4; j++) {
            const int seg = tid + j * 256;        // 0..1023
            const int arr = seg >> 9;             // 0:A 1:B
            const int w = seg & 511;
            const int r = w >> 2, c = w & 3;      // row 0..127, 16B chunk 0..3
            const __half* src = (arr == 0) ? g_x16 : g_w16;
            const int row = ((arr == 0) ? m0 : n0) + r;
            cp_async16(base + arr * TILE_B + r * ROWB + c * 16,
                       src + (size_t)row * K_TOT + kc + c * 8);
        }
        cp_commit();
    };

    float acc[4][4][4] = {};

    fill(0, 0);

    for (int i = 0; i < NITER; i++) {
        const int buf = i & 1;
        if (i + 1 < NITER) fill(i + 1, buf ^ 1);
        if (i + 1 < NITER) cp_wait1(); else cp_wait0();
        __syncthreads();

        const uint32_t sA = sbase + buf * BUF_B;
        const uint32_t sB = sA + TILE_B;

        uint32_t bf[4][4];
        #pragma unroll
        for (int nt = 0; nt < 4; nt++) {
            const int off = (wn0 + nt * 8 + (lane & 7)) * ROWB + (lane >> 3) * 16;
            ldmatrix_x4(bf[nt][0], bf[nt][1], bf[nt][2], bf[nt][3], sB + off);
        }

        #pragma unroll
        for (int ks = 0; ks < 2; ks++) {
            #pragma unroll
            for (int mt = 0; mt < 4; mt++) {
                const int off = (wm0 + mt * 16 + (lane & 15)) * ROWB
                              + ks * 32 + (lane >> 4) * 16;
                uint32_t a0, a1, a2, a3;
                ldmatrix_x4(a0, a1, a2, a3, sA + off);
                #pragma unroll
                for (int nt = 0; nt < 4; nt++) {
                    float* c = acc[mt][nt];
                    mma_f16(c[0], c[1], c[2], c[3], a0, a1, a2, a3,
                            bf[nt][ks * 2 + 0], bf[nt][ks * 2 + 1]);
                }
            }
        }
        __syncthreads();
    }

    // Epilogue: bias add; Q -> fp16 hi/lo split; K,V -> fp16 single.
    const int g  = lane >> 2;
    const int tq = lane & 3;
    #pragma unroll
    for (int nt = 0; nt < 4; nt++) {
        const int n = n0 + wn0 + nt * 8 + tq * 2;
        const float b0 = __ldg(bias + n);
        const float b1 = __ldg(bias + n + 1);
        const int three = n / C_;
        const int rem   = n - three * C_;
        const int head  = rem >> 6;
        const int d     = rem & 63;
        #pragma unroll
        for (int mt = 0; mt < 4; mt++) {
            #pragma unroll
            for (int half = 0; half < 2; half++) {
                const int m = m0 + wm0 + mt * 16 + g + half * 8;
                const int bb = m >> 10;
                const int t  = m & 1023;
                const float f0 = acc[mt][nt][half * 2 + 0] + b0;
                const float f1 = acc[mt][nt][half * 2 + 1] + b1;
                const size_t idx = ((size_t)(bb * H_ + head) * T_ + t) * HS_ + d;
                const __half h0 = __float2half_rn(f0);
                const __half h1 = __float2half_rn(f1);
                if (three == 0) {
                    const __half l0 = __float2half_rn(f0 - __half2float(h0));
                    const __half l1 = __float2half_rn(f1 - __half2float(h1));
                    *reinterpret_cast<__half2*>(g_Qh + idx) = __halves2half2(h0, h1);
                    *reinterpret_cast<__half2*>(g_Ql + idx) = __halves2half2(l0, l1);
                } else {
                    __half* dst = (three == 1) ? g_K16 : g_V16;
                    *reinterpret_cast<__half2*>(dst + idx) = __halves2half2(h0, h1);
                }
            }
        }
    }
}

// ---------------------------------------------------------------------------
// Kernel 2: fused causal ReLU attention — fp16, 2 passes per GEMM (unchanged).
// smem: Qh|Ql (16KB) + 2 x (K16|V16) buffers (2 x 16KB) = 48KB.
// ---------------------------------------------------------------------------
#define AT_BUF0  16384
#define AT_BUF_B 16384
#define AT_SMEM  49152

__global__ __launch_bounds__(128) void attn_hmma_kernel(float* __restrict__ out)
{
    extern __shared__ char smema[];
    const uint32_t sb = smem_u32(smema);
    const int tid  = threadIdx.x;
    const int warp = tid >> 5;
    const int lane = tid & 31;
    const int bh = blockIdx.x;
    const int qt = blockIdx.y;
    const int b  = bh / H_;
    const int h  = bh - b * H_;
    const size_t hbase = (size_t)bh * T_ * HS_;

    {
        #pragma unroll
        for (int j = 0; j < 8; j++) {
            const int seg = tid + j * 128;          // 0..1023
            const int arr = seg >> 9;               // 0:Qh 1:Ql
            const int w = seg & 511;
            const int r = w >> 3, c = w & 7;
            const __half* src = arr ? g_Ql : g_Qh;
            cp_async16(sb + arr * 8192 + SWZ128(r * 128 + c * 16),
                       src + hbase + (size_t)(qt * 64 + r) * HS_ + c * 8);
        }
    }
    auto fillkv = [&](int kt, int buf) {
        #pragma unroll
        for (int j = 0; j < 8; j++) {
            const int seg = tid + j * 128;          // 0..1023
            const int arr = seg >> 9;               // 0:K16 1:V16
            const int w = seg & 511;
            const int r = w >> 3, c = w & 7;
            const __half* src = arr ? g_V16 : g_K16;
            cp_async16(sb + AT_BUF0 + buf * AT_BUF_B + arr * 8192
                           + SWZ128(r * 128 + c * 16),
                       src + hbase + (size_t)(kt * 64 + r) * HS_ + c * 8);
        }
        cp_commit();
    };

    fillkv(0, 0);

    float y[8][4] = {};
    const float scale = 0.125f;
    const int rlo = warp * 16 + (lane >> 2);
    const int cbase = 2 * (lane & 3);

    for (int kt = 0; kt <= qt; kt++) {
        const int buf = kt & 1;
        if (kt < qt) { fillkv(kt + 1, buf ^ 1); cp_wait1(); }
        else         { cp_wait0(); }
        __syncthreads();

        const uint32_t sQh = sb, sQl = sb + 8192;
        const uint32_t sK = sb + AT_BUF0 + buf * AT_BUF_B;
        const uint32_t sV = sK + 8192;

        // ---- S = (Qh + Ql) · K16^T, 2 passes
        float S[8][4] = {};
        #pragma unroll
        for (int p = 0; p < 2; p++) {
            const uint32_t qb = p ? sQl : sQh;
            uint32_t af[4][4];
            #pragma unroll
            for (int ks = 0; ks < 4; ks++) {
                const int row = warp * 16 + (lane & 15);
                const int colb = ks * 32 + (lane >> 4) * 16;
                ldmatrix_x4(af[ks][0], af[ks][1], af[ks][2], af[ks][3],
                            qb + SWZ128(row * 128 + colb));
            }
            #pragma unroll
            for (int kp = 0; kp < 2; kp++) {
                uint32_t bs[8][4];
                #pragma unroll
                for (int nt = 0; nt < 8; nt++) {
                    const int row = nt * 8 + (lane & 7);
                    const int colb = kp * 64 + (lane >> 3) * 16;
                    ldmatrix_x4(bs[nt][0], bs[nt][1], bs[nt][2], bs[nt][3],
                                sK + SWZ128(row * 128 + colb));
                }
                #pragma unroll
                for (int nt = 0; nt < 8; nt++) {
                    mma_f16(S[nt][0], S[nt][1], S[nt][2], S[nt][3],
                            af[2*kp][0], af[2*kp][1], af[2*kp][2], af[2*kp][3],
                            bs[nt][0], bs[nt][1]);
                    mma_f16(S[nt][0], S[nt][1], S[nt][2], S[nt][3],
                            af[2*kp+1][0], af[2*kp+1][1], af[2*kp+1][2], af[2*kp+1][3],
                            bs[nt][2], bs[nt][3]);
                }
            }
        }

        // ---- P = relu(scale*S), causal mask; split fp16 + repack to A frags
        const bool diag = (kt == qt);
        uint32_t pha[4][4], pla[4][4];
        #pragma unroll
        for (int ksp = 0; ksp < 4; ksp++) {
            #pragma unroll
            for (int u = 0; u < 2; u++) {
                const int ntile = 2 * ksp + u;
                float pv[4];
                #pragma unroll
                for (int c = 0; c < 4; c++) {
                    float v = fmaxf(S[ntile][c] * scale, 0.0f);
                    if (diag) {
                        const int col = ntile * 8 + cbase + (c & 1);
                        const int row = rlo + ((c >= 2) ? 8 : 0);
                        if (col > row) v = 0.0f;
                    }
                    pv[c] = v;
                }
                __half h0 = __float2half_rn(pv[0]);
                __half h1 = __float2half_rn(pv[1]);
                __half h2 = __float2half_rn(pv[2]);
                __half h3 = __float2half_rn(pv[3]);
                pha[ksp][2*u + 0] = pk_h2(h0, h1);
                pha[ksp][2*u + 1] = pk_h2(h2, h3);
                pla[ksp][2*u + 0] = pk_h2(
                    __float2half_rn(pv[0] - __half2float(h0)),
                    __float2half_rn(pv[1] - __half2float(h1)));
                pla[ksp][2*u + 1] = pk_h2(
                    __float2half_rn(pv[2] - __half2float(h2)),
                    __float2half_rn(pv[3] - __half2float(h3)));
            }
        }

        // ---- y += (Ph + Pl) · V16, 2 passes; V frags via ldmatrix.trans
        #pragma unroll
        for (int p = 0; p < 2; p++) {
            const uint32_t (*pa)[4] = p ? pla : pha;
            #pragma unroll
            for (int kp = 0; kp < 2; kp++) {
                uint32_t bv[8][4];
                #pragma unroll
                for (int nt = 0; nt < 8; nt++) {
                    const int row = kp * 32 + (lane >> 3) * 8 + (lane & 7);
                    const int colb = nt * 16;
                    ldmatrix_x4_trans(bv[nt][0], bv[nt][1], bv[nt][2], bv[nt][3],
                                      sV + SWZ128(row * 128 + colb));
                }
                #pragma unroll
                for (int nt = 0; nt < 8; nt++) {
                    mma_f16(y[nt][0], y[nt][1], y[nt][2], y[nt][3],
                            pa[2*kp][0], pa[2*kp][1], pa[2*kp][2], pa[2*kp][3],
                            bv[nt][0], bv[nt][1]);
                    mma_f16(y[nt][0], y[nt][1], y[nt][2], y[nt][3],
                            pa[2*kp+1][0], pa[2*kp+1][1], pa[2*kp+1][2], pa[2*kp+1][3],
                            bv[nt][2], bv[nt][3]);
                }
            }
        }
        __syncthreads();
    }

    const int g = lane >> 2;
    #pragma unroll
    for (int nt = 0; nt < 8; nt++) {
        const int col = h * HS_ + nt * 8 + cbase;
        const int t0 = qt * 64 + warp * 16 + g;
        float2 v0; v0.x = y[nt][0]; v0.y = y[nt][1];
        float2 v1; v1.x = y[nt][2]; v1.y = y[nt][3];
        *reinterpret_cast<float2*>(out + ((size_t)b * T_ + t0) * C_ + col) = v0;
        *reinterpret_cast<float2*>(out + ((size_t)b * T_ + t0 + 8) * C_ + col) = v1;
    }
}

// ---------------------------------------------------------------------------
extern "C" void kernel_launch(void* const* d_in, const int* in_sizes, int n_in,
                              void* d_out, int out_size)
{
    const float* x    = (const float*)d_in[0];
    const float* W    = (const float*)d_in[1];
    const float* bias = (const float*)d_in[2];
    float* out = (float*)d_out;

    split_kernel<<<1184, 256>>>(x, W);

    cudaFuncSetAttribute(qkv_hmma_kernel,
                         cudaFuncAttributeMaxDynamicSharedMemorySize, GEMM_SMEM);
    qkv_hmma_kernel<<<dim3(N_TOT / 128, M_TOT / 128), 256, GEMM_SMEM>>>(bias);

    cudaFuncSetAttribute(attn_hmma_kernel,
                         cudaFuncAttributeMaxDynamicSharedMemorySize, AT_SMEM);
    attn_hmma_kernel<<<dim3(B_ * H_, T_ / 64), 128, AT_SMEM>>>(out);
}

// round 9
// speedup vs baseline: 2.9196x; 1.3234x over previous
#include <cuda_runtime.h>
#include <cuda_fp16.h>
#include <cstdint>

// Problem constants
#define B_  8
#define T_  1024
#define C_  768
#define H_  12
#define HS_ 64
#define M_TOT (B_*T_)        // 8192
#define N_TOT (3*C_)         // 2304
#define K_TOT C_             // 768

// ---------------------------------------------------------------------------
// Device-global scratch (fp16 single plane)
// ---------------------------------------------------------------------------
__device__ __align__(16) __half g_Q16[B_*H_*T_*HS_];
__device__ __align__(16) __half g_K16[B_*H_*T_*HS_];
__device__ __align__(16) __half g_V16[B_*H_*T_*HS_];

__device__ __align__(16) __half g_x16[M_TOT*K_TOT];
__device__ __align__(16) __half g_w16[N_TOT*K_TOT];

// ---------------------------------------------------------------------------
// PTX helpers (base ISA only)
// ---------------------------------------------------------------------------
__device__ __forceinline__ uint32_t smem_u32(const void* p) {
    uint32_t a;
    asm("{ .reg .u64 t; cvta.to.shared.u64 t, %1; cvt.u32.u64 %0, t; }"
        : "=r"(a) : "l"(p));
    return a;
}
__device__ __forceinline__ void cp_async16(uint32_t s, const void* g) {
    asm volatile("cp.async.cg.shared.global [%0], [%1], 16;" :: "r"(s), "l"(g));
}
__device__ __forceinline__ void cp_commit() {
    asm volatile("cp.async.commit_group;" ::: "memory");
}
__device__ __forceinline__ void cp_wait1() {
    asm volatile("cp.async.wait_group 1;" ::: "memory");
}
__device__ __forceinline__ void cp_wait0() {
    asm volatile("cp.async.wait_group 0;" ::: "memory");
}
__device__ __forceinline__ void ldmatrix_x4(uint32_t& r0, uint32_t& r1,
                                            uint32_t& r2, uint32_t& r3,
                                            uint32_t addr) {
    asm volatile("ldmatrix.sync.aligned.m8n8.x4.shared.b16 {%0,%1,%2,%3}, [%4];"
                 : "=r"(r0), "=r"(r1), "=r"(r2), "=r"(r3) : "r"(addr));
}
__device__ __forceinline__ void ldmatrix_x4_trans(uint32_t& r0, uint32_t& r1,
                                                  uint32_t& r2, uint32_t& r3,
                                                  uint32_t addr) {
    asm volatile("ldmatrix.sync.aligned.m8n8.x4.trans.shared.b16 {%0,%1,%2,%3}, [%4];"
                 : "=r"(r0), "=r"(r1), "=r"(r2), "=r"(r3) : "r"(addr));
}
__device__ __forceinline__ void mma_f16(float& c0, float& c1, float& c2, float& c3,
                                        uint32_t a0, uint32_t a1, uint32_t a2, uint32_t a3,
                                        uint32_t b0, uint32_t b1) {
    asm volatile(
        "mma.sync.aligned.m16n8k16.row.col.f32.f16.f16.f32 "
        "{%0,%1,%2,%3}, {%4,%5,%6,%7}, {%8,%9}, {%0,%1,%2,%3};"
        : "+f"(c0), "+f"(c1), "+f"(c2), "+f"(c3)
        : "r"(a0), "r"(a1), "r"(a2), "r"(a3), "r"(b0), "r"(b1));
}
__device__ __forceinline__ uint32_t pk_h2(__half lo, __half hi) {
    __half2 v = __halves2half2(lo, hi);
    return *reinterpret_cast<uint32_t*>(&v);
}
#define SWZ128(o) ((o) ^ (((o) >> 3) & 0x70))

// ---------------------------------------------------------------------------
// Kernel 0: fp32 -> fp16 single plane for x and W
// ---------------------------------------------------------------------------
__global__ __launch_bounds__(256) void split_kernel(const float* __restrict__ x,
                                                    const float* __restrict__ W)
{
    const int nqx = (M_TOT * K_TOT) / 4;
    const int nqw = (N_TOT * K_TOT) / 4;
    for (int q = blockIdx.x * blockDim.x + threadIdx.x; q < nqx + nqw;
         q += gridDim.x * blockDim.x) {
        const float4* src; __half* dst; int qq;
        if (q < nqx) { src = (const float4*)x; dst = g_x16; qq = q; }
        else         { src = (const float4*)W; dst = g_w16; qq = q - nqx; }
        const float4 v = src[qq];
        __half2* p = (__half2*)(dst + (size_t)qq * 4);
        p[0] = __halves2half2(__float2half_rn(v.x), __float2half_rn(v.y));
        p[1] = __halves2half2(__float2half_rn(v.z), __float2half_rn(v.w));
    }
}

// ---------------------------------------------------------------------------
// Kernel 1: HMMA QKV GEMM — fp16 single pass (x16 · w16).
// ---------------------------------------------------------------------------
#define ROWB 80
#define TILE_B (128*ROWB)
#define BUF_B  (2*TILE_B)
#define GEMM_SMEM (2*BUF_B)
#define NITER  24

__global__ __launch_bounds__(256) void qkv_hmma_kernel(const float* __restrict__ bias)
{
    extern __shared__ char smg[];
    const uint32_t sbase = smem_u32(smg);

    const int tid  = threadIdx.x;
    const int warp = tid >> 5;
    const int lane = tid & 31;
    const int m0 = blockIdx.y * 128;
    const int n0 = blockIdx.x * 128;
    const int wm0 = (warp >> 2) * 64;
    const int wn0 = (warp & 3) * 32;

    auto fill = [&](int it, int buf) {
        const int kc = it * 32;
        const uint32_t base = sbase + buf * BUF_B;
        #pragma unroll
        for (int j = 0; j < 4; j++) {
            const int seg = tid + j * 256;
            const int arr = seg >> 9;
            const int w = seg & 511;
            const int r = w >> 2, c = w & 3;
            const __half* src = (arr == 0) ? g_x16 : g_w16;
            const int row = ((arr == 0) ? m0 : n0) + r;
            cp_async16(base + arr * TILE_B + r * ROWB + c * 16,
                       src + (size_t)row * K_TOT + kc + c * 8);
        }
        cp_commit();
    };

    float acc[4][4][4] = {};

    fill(0, 0);

    for (int i = 0; i < NITER; i++) {
        const int buf = i & 1;
        if (i + 1 < NITER) fill(i + 1, buf ^ 1);
        if (i + 1 < NITER) cp_wait1(); else cp_wait0();
        __syncthreads();

        const uint32_t sA = sbase + buf * BUF_B;
        const uint32_t sB = sA + TILE_B;

        uint32_t bf[4][4];
        #pragma unroll
        for (int nt = 0; nt < 4; nt++) {
            const int off = (wn0 + nt * 8 + (lane & 7)) * ROWB + (lane >> 3) * 16;
            ldmatrix_x4(bf[nt][0], bf[nt][1], bf[nt][2], bf[nt][3], sB + off);
        }

        #pragma unroll
        for (int ks = 0; ks < 2; ks++) {
            #pragma unroll
            for (int mt = 0; mt < 4; mt++) {
                const int off = (wm0 + mt * 16 + (lane & 15)) * ROWB
                              + ks * 32 + (lane >> 4) * 16;
                uint32_t a0, a1, a2, a3;
                ldmatrix_x4(a0, a1, a2, a3, sA + off);
                #pragma unroll
                for (int nt = 0; nt < 4; nt++) {
                    float* c = acc[mt][nt];
                    mma_f16(c[0], c[1], c[2], c[3], a0, a1, a2, a3,
                            bf[nt][ks * 2 + 0], bf[nt][ks * 2 + 1]);
                }
            }
        }
        __syncthreads();
    }

    // Epilogue: bias add; Q/K/V -> fp16 single plane, scatter [B,H,T,hs]
    const int g  = lane >> 2;
    const int tq = lane & 3;
    #pragma unroll
    for (int nt = 0; nt < 4; nt++) {
        const int n = n0 + wn0 + nt * 8 + tq * 2;
        const float b0 = __ldg(bias + n);
        const float b1 = __ldg(bias + n + 1);
        const int three = n / C_;
        const int rem   = n - three * C_;
        const int head  = rem >> 6;
        const int d     = rem & 63;
        __half* dst = (three == 0) ? g_Q16 : (three == 1) ? g_K16 : g_V16;
        #pragma unroll
        for (int mt = 0; mt < 4; mt++) {
            #pragma unroll
            for (int half = 0; half < 2; half++) {
                const int m = m0 + wm0 + mt * 16 + g + half * 8;
                const int bb = m >> 10;
                const int t  = m & 1023;
                const float f0 = acc[mt][nt][half * 2 + 0] + b0;
                const float f1 = acc[mt][nt][half * 2 + 1] + b1;
                const size_t idx = ((size_t)(bb * H_ + head) * T_ + t) * HS_ + d;
                *reinterpret_cast<__half2*>(dst + idx) =
                    __halves2half2(__float2half_rn(f0), __float2half_rn(f1));
            }
        }
    }
}

// ---------------------------------------------------------------------------
// Kernel 2: fused causal ReLU attention — fp16 single pass per GEMM.
// smem: Q16 (8KB) + 2 x (K16|V16) buffers (2 x 16KB) = 40KB.
// ---------------------------------------------------------------------------
#define AT_BUF0  8192
#define AT_BUF_B 16384
#define AT_SMEM  40960

__global__ __launch_bounds__(128) void attn_hmma_kernel(float* __restrict__ out)
{
    extern __shared__ char smema[];
    const uint32_t sb = smem_u32(smema);
    const int tid  = threadIdx.x;
    const int warp = tid >> 5;
    const int lane = tid & 31;
    const int bh = blockIdx.x;
    const int qt = (int)gridDim.y - 1 - (int)blockIdx.y;  // heavy tiles first
    const int b  = bh / H_;
    const int h  = bh - b * H_;
    const size_t hbase = (size_t)bh * T_ * HS_;

    // ---- load Q tile (single plane), swizzled 128B rows
    {
        #pragma unroll
        for (int j = 0; j < 4; j++) {
            const int w = tid + j * 128;            // 0..511
            const int r = w >> 3, c = w & 7;
            cp_async16(sb + SWZ128(r * 128 + c * 16),
                       g_Q16 + hbase + (size_t)(qt * 64 + r) * HS_ + c * 8);
        }
    }
    auto fillkv = [&](int kt, int buf) {
        #pragma unroll
        for (int j = 0; j < 8; j++) {
            const int seg = tid + j * 128;          // 0..1023
            const int arr = seg >> 9;               // 0:K16 1:V16
            const int w = seg & 511;
            const int r = w >> 3, c = w & 7;
            const __half* src = arr ? g_V16 : g_K16;
            cp_async16(sb + AT_BUF0 + buf * AT_BUF_B + arr * 8192
                           + SWZ128(r * 128 + c * 16),
                       src + hbase + (size_t)(kt * 64 + r) * HS_ + c * 8);
        }
        cp_commit();
    };

    fillkv(0, 0);   // Q loads ride in this group

    float y[8][4] = {};
    const float scale = 0.125f;
    const int rlo = warp * 16 + (lane >> 2);
    const int cbase = 2 * (lane & 3);

    for (int kt = 0; kt <= qt; kt++) {
        const int buf = kt & 1;
        if (kt < qt) { fillkv(kt + 1, buf ^ 1); cp_wait1(); }
        else         { cp_wait0(); }
        __syncthreads();

        const uint32_t sQ = sb;
        const uint32_t sK = sb + AT_BUF0 + buf * AT_BUF_B;
        const uint32_t sV = sK + 8192;

        // ---- S = Q16 · K16^T (single pass)
        float S[8][4] = {};
        uint32_t af[4][4];
        #pragma unroll
        for (int ks = 0; ks < 4; ks++) {
            const int row = warp * 16 + (lane & 15);
            const int colb = ks * 32 + (lane >> 4) * 16;
            ldmatrix_x4(af[ks][0], af[ks][1], af[ks][2], af[ks][3],
                        sQ + SWZ128(row * 128 + colb));
        }
        #pragma unroll
        for (int kp = 0; kp < 2; kp++) {
            uint32_t bs[8][4];
            #pragma unroll
            for (int nt = 0; nt < 8; nt++) {
                const int row = nt * 8 + (lane & 7);
                const int colb = kp * 64 + (lane >> 3) * 16;
                ldmatrix_x4(bs[nt][0], bs[nt][1], bs[nt][2], bs[nt][3],
                            sK + SWZ128(row * 128 + colb));
            }
            #pragma unroll
            for (int nt = 0; nt < 8; nt++) {
                mma_f16(S[nt][0], S[nt][1], S[nt][2], S[nt][3],
                        af[2*kp][0], af[2*kp][1], af[2*kp][2], af[2*kp][3],
                        bs[nt][0], bs[nt][1]);
                mma_f16(S[nt][0], S[nt][1], S[nt][2], S[nt][3],
                        af[2*kp+1][0], af[2*kp+1][1], af[2*kp+1][2], af[2*kp+1][3],
                        bs[nt][2], bs[nt][3]);
            }
        }

        // ---- P = relu(scale*S), causal mask; round fp16 + repack to A frags
        const bool diag = (kt == qt);
        uint32_t pha[4][4];
        #pragma unroll
        for (int ksp = 0; ksp < 4; ksp++) {
            #pragma unroll
            for (int u = 0; u < 2; u++) {
                const int ntile = 2 * ksp + u;
                float pv[4];
                #pragma unroll
                for (int c = 0; c < 4; c++) {
                    float v = fmaxf(S[ntile][c] * scale, 0.0f);
                    if (diag) {
                        const int col = ntile * 8 + cbase + (c & 1);
                        const int row = rlo + ((c >= 2) ? 8 : 0);
                        if (col > row) v = 0.0f;
                    }
                    pv[c] = v;
                }
                pha[ksp][2*u + 0] = pk_h2(__float2half_rn(pv[0]), __float2half_rn(pv[1]));
                pha[ksp][2*u + 1] = pk_h2(__float2half_rn(pv[2]), __float2half_rn(pv[3]));
            }
        }

        // ---- y += P16 · V16 (single pass); V frags via ldmatrix.trans
        #pragma unroll
        for (int kp = 0; kp < 2; kp++) {
            uint32_t bv[8][4];
            #pragma unroll
            for (int nt = 0; nt < 8; nt++) {
                const int row = kp * 32 + (lane >> 3) * 8 + (lane & 7);
                const int colb = nt * 16;
                ldmatrix_x4_trans(bv[nt][0], bv[nt][1], bv[nt][2], bv[nt][3],
                                  sV + SWZ128(row * 128 + colb));
            }
            #pragma unroll
            for (int nt = 0; nt < 8; nt++) {
                mma_f16(y[nt][0], y[nt][1], y[nt][2], y[nt][3],
                        pha[2*kp][0], pha[2*kp][1], pha[2*kp][2], pha[2*kp][3],
                        bv[nt][0], bv[nt][1]);
                mma_f16(y[nt][0], y[nt][1], y[nt][2], y[nt][3],
                        pha[2*kp+1][0], pha[2*kp+1][1], pha[2*kp+1][2], pha[2*kp+1][3],
                        bv[nt][2], bv[nt][3]);
            }
        }
        __syncthreads();
    }

    const int g = lane >> 2;
    #pragma unroll
    for (int nt = 0; nt < 8; nt++) {
        const int col = h * HS_ + nt * 8 + cbase;
        const int t0 = qt * 64 + warp * 16 + g;
        float2 v0; v0.x = y[nt][0]; v0.y = y[nt][1];
        float2 v1; v1.x = y[nt][2]; v1.y = y[nt][3];
        *reinterpret_cast<float2*>(out + ((size_t)b * T_ + t0) * C_ + col) = v0;
        *reinterpret_cast<float2*>(out + ((size_t)b * T_ + t0 + 8) * C_ + col) = v1;
    }
}

// ---------------------------------------------------------------------------
extern "C" void kernel_launch(void* const* d_in, const int* in_sizes, int n_in,
                              void* d_out, int out_size)
{
    const float* x    = (const float*)d_in[0];
    const float* W    = (const float*)d_in[1];
    const float* bias = (const float*)d_in[2];
    float* out = (float*)d_out;

    split_kernel<<<1184, 256>>>(x, W);

    cudaFuncSetAttribute(qkv_hmma_kernel,
                         cudaFuncAttributeMaxDynamicSharedMemorySize, GEMM_SMEM);
    qkv_hmma_kernel<<<dim3(N_TOT / 128, M_TOT / 128), 256, GEMM_SMEM>>>(bias);

    cudaFuncSetAttribute(attn_hmma_kernel,
                         cudaFuncAttributeMaxDynamicSharedMemorySize, AT_SMEM);
    attn_hmma_kernel<<<dim3(B_ * H_, T_ / 64), 128, AT_SMEM>>>(out);
}